// round 3
// baseline (speedup 1.0000x reference)
#include <cuda_runtime.h>
#include <cstdint>

#define N_NODES 30000
#define E_RAW   480000
#define E_TOT   (E_RAW + N_NODES)
#define DIM     512
#define HEADS   8
#define CH      64
#define NH      (N_NODES * HEADS)
#define TOTAL   ((long)N_NODES * DIM)

// ---------------- scratch (device globals; no allocations) ----------------
__device__ float    g_h   [(size_t)N_NODES * DIM];
__device__ float    g_xp  [(size_t)N_NODES * DIM];
__device__ float    g_out1[(size_t)N_NODES * DIM];   // layer out accumulator
__device__ float    g_as  [NH];
__device__ float    g_ad  [NH];
__device__ float    g_m   [NH];
__device__ float    g_s   [NH];
__device__ unsigned g_menc[NH];
__device__ float    g_e   [(size_t)E_TOT * HEADS];
__device__ int      g_w64;   // 1 if edge_index buffer is int64, 0 if int32

// ---------------- threefry2x32 (bit-exact JAX) ----------------
__host__ __device__ __forceinline__ uint32_t rotl32(uint32_t v, int r) {
    return (v << r) | (v >> (32 - r));
}

__host__ __device__ __forceinline__ void threefry2x32_fn(
    uint32_t k0, uint32_t k1, uint32_t x0, uint32_t x1,
    uint32_t& o0, uint32_t& o1)
{
    uint32_t ks2 = k0 ^ k1 ^ 0x1BD11BDAu;
    x0 += k0; x1 += k1;
#define TFR(r) { x0 += x1; x1 = rotl32(x1, r); x1 ^= x0; }
    TFR(13) TFR(15) TFR(26) TFR(6)   x0 += k1;  x1 += ks2 + 1u;
    TFR(17) TFR(29) TFR(16) TFR(24)  x0 += ks2; x1 += k0  + 2u;
    TFR(13) TFR(15) TFR(26) TFR(6)   x0 += k0;  x1 += k1  + 3u;
    TFR(17) TFR(29) TFR(16) TFR(24)  x0 += k1;  x1 += ks2 + 4u;
    TFR(13) TFR(15) TFR(26) TFR(6)   x0 += ks2; x1 += k0  + 5u;
#undef TFR
    o0 = x0; o1 = x1;
}

// ---------------- edge dtype detection ----------------
__global__ void k_detect(const int* __restrict__ ei32)
{
    if (threadIdx.x == 0 && blockIdx.x == 0) {
        int w = 1;
        #pragma unroll 1
        for (int i = 0; i < 64; i++)
            if (ei32[2 * i + 1] != 0) { w = 0; break; }
        g_w64 = w;
    }
}

__device__ __forceinline__ void edge_endpoints(const int* __restrict__ ei32,
                                               int e, int& s, int& d)
{
    if (e >= E_RAW) { s = d = e - E_RAW; return; }
    if (g_w64) { s = ei32[2 * e]; d = ei32[2 * (E_RAW + e)]; }
    else       { s = ei32[e];     d = ei32[E_RAW + e]; }
}

// ---------------- fused dropout + (bias) + ELU ----------------
// JAX threefry_partitionable random_bits (32-bit): per element i,
//   (o0, o1) = threefry2x32(key, hi=0, lo=i);  bits = o0 ^ o1
__global__ void k_dropelu(const float* __restrict__ in,
                          const float* __restrict__ bias,
                          int internal, uint32_t k0, uint32_t k1)
{
    long i = (long)blockIdx.x * blockDim.x + threadIdx.x;
    if (i >= TOTAL) return;
    float v;
    if (internal) v = g_out1[i] + bias[i & (DIM - 1)];
    else          v = in[i];

    uint32_t o0, o1;
    threefry2x32_fn(k0, k1, 0u, (uint32_t)i, o0, o1);
    uint32_t bits = o0 ^ o1;
    float u = __uint_as_float((bits >> 9) | 0x3f800000u) - 1.0f;

    v = (u < 0.8f) ? v * 1.25f : 0.0f;            // dropout p=0.2, scale 1/0.8
    g_h[i] = (v > 0.0f) ? v : expm1f(v);           // ELU
}

// ---------------- SGEMM: g_xp = g_h (MxK) @ B (KxN), K=N=512 ----------------
__global__ void k_sgemm(const float* __restrict__ B, int M)
{
    const int K = DIM, Nc = DIM;
    __shared__ float As[64][33];   // [row][k] padded
    __shared__ float Bs[32][64];   // [k][col]
    int tid = threadIdx.x;
    int tx = tid & 15, ty = tid >> 4;
    int rowBase = blockIdx.y * 64, colBase = blockIdx.x * 64;

    float acc[4][4] = {};
    for (int k0 = 0; k0 < K; k0 += 32) {
        #pragma unroll
        for (int it = 0; it < 8; it++) {
            int idx = tid + it * 256;          // 2048 = 64 rows x 32 k
            int r = idx >> 5, kk = idx & 31;
            int gr = rowBase + r;
            As[r][kk] = (gr < M) ? g_h[(long)gr * K + k0 + kk] : 0.0f;
        }
        #pragma unroll
        for (int it = 0; it < 8; it++) {
            int idx = tid + it * 256;          // 2048 = 32 k x 64 cols
            int kk = idx >> 6, c = idx & 63;
            Bs[kk][c] = B[(long)(k0 + kk) * Nc + colBase + c];
        }
        __syncthreads();
        #pragma unroll
        for (int kk = 0; kk < 32; kk++) {
            float a0 = As[ty * 4 + 0][kk];
            float a1 = As[ty * 4 + 1][kk];
            float a2 = As[ty * 4 + 2][kk];
            float a3 = As[ty * 4 + 3][kk];
            float4 b4 = *(const float4*)&Bs[kk][tx * 4];
            acc[0][0] += a0 * b4.x; acc[0][1] += a0 * b4.y; acc[0][2] += a0 * b4.z; acc[0][3] += a0 * b4.w;
            acc[1][0] += a1 * b4.x; acc[1][1] += a1 * b4.y; acc[1][2] += a1 * b4.z; acc[1][3] += a1 * b4.w;
            acc[2][0] += a2 * b4.x; acc[2][1] += a2 * b4.y; acc[2][2] += a2 * b4.z; acc[2][3] += a2 * b4.w;
            acc[3][0] += a3 * b4.x; acc[3][1] += a3 * b4.y; acc[3][2] += a3 * b4.z; acc[3][3] += a3 * b4.w;
        }
        __syncthreads();
    }
    #pragma unroll
    for (int i = 0; i < 4; i++) {
        int gr = rowBase + ty * 4 + i;
        if (gr < M) {
            float4 v = make_float4(acc[i][0], acc[i][1], acc[i][2], acc[i][3]);
            *(float4*)&g_xp[(long)gr * Nc + colBase + tx * 4] = v;
        }
    }
}

// ---------------- per-(node,head) attention dot products ----------------
__global__ void k_attdot(const float* __restrict__ asrc, const float* __restrict__ adst)
{
    int n = blockIdx.x;
    int h = threadIdx.x >> 5;
    int lane = threadIdx.x & 31;
    const float* row = g_xp + (long)n * DIM + h * CH;
    float v0 = row[lane], v1 = row[lane + 32];
    float s = v0 * asrc[h * CH + lane] + v1 * asrc[h * CH + lane + 32];
    float d = v0 * adst[h * CH + lane] + v1 * adst[h * CH + lane + 32];
    #pragma unroll
    for (int o = 16; o; o >>= 1) {
        s += __shfl_xor_sync(0xFFFFFFFFu, s, o);
        d += __shfl_xor_sync(0xFFFFFFFFu, d, o);
    }
    if (lane == 0) { g_as[n * HEADS + h] = s; g_ad[n * HEADS + h] = d; }
}

// ---------------- init: zero out1/s, menc = enc(-inf) ----------------
__global__ void k_init()
{
    long i = (long)blockIdx.x * blockDim.x + threadIdx.x;
    if (i >= TOTAL) return;
    g_out1[i] = 0.0f;
    if (i < NH) { g_menc[i] = 0x007FFFFFu; g_s[i] = 0.0f; }
}

// ---------------- edge pass 1: leaky-relu logit + segment max ----------------
__global__ void k_edge1(const int* __restrict__ ei32)
{
    int e = blockIdx.x * blockDim.x + threadIdx.x;
    if (e >= E_TOT) return;
    int sn, dn; edge_endpoints(ei32, e, sn, dn);
    float4 sa = *(const float4*)(g_as + sn * HEADS);
    float4 sb = *(const float4*)(g_as + sn * HEADS + 4);
    float4 da = *(const float4*)(g_ad + dn * HEADS);
    float4 db = *(const float4*)(g_ad + dn * HEADS + 4);
    float v[HEADS] = { sa.x + da.x, sa.y + da.y, sa.z + da.z, sa.w + da.w,
                       sb.x + db.x, sb.y + db.y, sb.z + db.z, sb.w + db.w };
    #pragma unroll
    for (int h = 0; h < HEADS; h++) {
        float lv = (v[h] > 0.0f) ? v[h] : 0.2f * v[h];
        g_e[(long)e * HEADS + h] = lv;
        unsigned b = __float_as_uint(lv);
        unsigned enc = (b & 0x80000000u) ? ~b : (b | 0x80000000u);
        atomicMax(&g_menc[dn * HEADS + h], enc);
    }
}

// ---------------- decode monotone-encoded max ----------------
__global__ void k_decode()
{
    int i = blockIdx.x * blockDim.x + threadIdx.x;
    if (i >= NH) return;
    unsigned enc = g_menc[i];
    unsigned b = (enc & 0x80000000u) ? (enc & 0x7FFFFFFFu) : ~enc;
    g_m[i] = __uint_as_float(b);
}

// ---------------- edge pass 2: exp + segment sum ----------------
__global__ void k_edge2(const int* __restrict__ ei32)
{
    int e = blockIdx.x * blockDim.x + threadIdx.x;
    if (e >= E_TOT) return;
    int sn, dn; edge_endpoints(ei32, e, sn, dn);
    #pragma unroll
    for (int h = 0; h < HEADS; h++) {
        float p = expf(g_e[(long)e * HEADS + h] - g_m[dn * HEADS + h]);
        g_e[(long)e * HEADS + h] = p;
        atomicAdd(&g_s[dn * HEADS + h], p);
    }
}

// ---------------- message scatter: one warp per (edge, head) ----------------
__global__ void k_msg(const int* __restrict__ ei32)
{
    int e = blockIdx.x;
    int h = threadIdx.x >> 5;
    int lane = threadIdx.x & 31;
    int sn, dn; edge_endpoints(ei32, e, sn, dn);
    float alpha = g_e[(long)e * HEADS + h] / (g_s[dn * HEADS + h] + 1e-16f);
    const float2* src = (const float2*)(g_xp + (long)sn * DIM + h * CH);
    float2 v = src[lane];
    float* dst = g_out1 + (long)dn * DIM + h * CH + lane * 2;
    atomicAdd(dst,     alpha * v.x);
    atomicAdd(dst + 1, alpha * v.y);
}

// ---------------- final: mean over heads + bias ----------------
__global__ void k_final(const float* __restrict__ b2, float* __restrict__ out)
{
    int i = blockIdx.x * blockDim.x + threadIdx.x;
    if (i >= N_NODES * CH) return;
    int n = i >> 6, c = i & 63;
    float acc = 0.0f;
    #pragma unroll
    for (int h = 0; h < HEADS; h++)
        acc += g_out1[(long)n * DIM + h * CH + c];
    out[i] = acc * 0.125f + b2[c];
}

// ---------------- host orchestration ----------------
extern "C" void kernel_launch(void* const* d_in, const int* in_sizes, int n_in,
                              void* d_out, int out_size)
{
    const float* x   = (const float*)d_in[0];
    const int*   ei  = (const int*)d_in[1];     // int32 or int64 view; detected on device
    const float* W1  = (const float*)d_in[2];
    const float* as1 = (const float*)d_in[3];
    const float* ad1 = (const float*)d_in[4];
    const float* b1  = (const float*)d_in[5];
    const float* W2  = (const float*)d_in[6];
    const float* as2 = (const float*)d_in[7];
    const float* ad2 = (const float*)d_in[8];
    const float* b2  = (const float*)d_in[9];
    float*       out = (float*)d_out;

    // Key derivation, threefry_partitionable (fold-like split):
    //   key(42) = (0, 42);  split -> key_j = threefry2x32(key, 0, j) full pair
    uint32_t k1a, k1b, k2a, k2b;
    threefry2x32_fn(0u, 42u, 0u, 0u, k1a, k1b);   // k1 = (o0, o1) of counter 0
    threefry2x32_fn(0u, 42u, 0u, 1u, k2a, k2b);   // k2 = (o0, o1) of counter 1

    const int elemBlocks = (int)((TOTAL + 255) / 256);
    const int edgeBlocks = (E_TOT + 255) / 256;
    const int nhBlocks   = (NH + 255) / 256;
    dim3 gemmGrid(DIM / 64, (N_NODES + 63) / 64);

    k_detect<<<1, 32>>>(ei);

    // ---- layer 1 ----
    k_dropelu<<<elemBlocks, 256>>>(x, nullptr, 0, k1a, k1b);
    k_sgemm<<<gemmGrid, 256>>>(W1, N_NODES);
    k_attdot<<<N_NODES, 256>>>(as1, ad1);
    k_init<<<elemBlocks, 256>>>();
    k_edge1<<<edgeBlocks, 256>>>(ei);
    k_decode<<<nhBlocks, 256>>>();
    k_edge2<<<edgeBlocks, 256>>>(ei);
    k_msg<<<E_TOT, 256>>>(ei);

    // ---- layer 2 ----
    k_dropelu<<<elemBlocks, 256>>>(nullptr, b1, 1, k2a, k2b);
    k_sgemm<<<gemmGrid, 256>>>(W2, N_NODES);
    k_attdot<<<N_NODES, 256>>>(as2, ad2);
    k_init<<<elemBlocks, 256>>>();
    k_edge1<<<edgeBlocks, 256>>>(ei);
    k_decode<<<nhBlocks, 256>>>();
    k_edge2<<<edgeBlocks, 256>>>(ei);
    k_msg<<<E_TOT, 256>>>(ei);

    k_final<<<(N_NODES * CH + 255) / 256, 256>>>(b2, out);
}

// round 4
// speedup vs baseline: 2.0167x; 2.0167x over previous
#include <cuda_runtime.h>
#include <cstdint>

#define N_NODES 30000
#define E_RAW   480000
#define E_TOT   (E_RAW + N_NODES)
#define DIM     512
#define HEADS   8
#define CH      64
#define NH      (N_NODES * HEADS)
#define TOTAL   ((long)N_NODES * DIM)

// ---------------- scratch (device globals; no allocations) ----------------
__device__ float g_h   [(size_t)N_NODES * DIM];
__device__ float g_xp  [(size_t)N_NODES * DIM];
__device__ float g_out1[(size_t)N_NODES * DIM];
__device__ float g_as  [NH];
__device__ float g_ad  [NH];
__device__ int   g_deg [N_NODES];
__device__ int   g_cur [N_NODES];
__device__ int   g_rowptr[N_NODES + 1];
__device__ int   g_csrc[E_TOT];
__device__ int   g_w64;

// ---------------- threefry2x32 (bit-exact JAX, partitionable) ----------------
__host__ __device__ __forceinline__ uint32_t rotl32(uint32_t v, int r) {
    return (v << r) | (v >> (32 - r));
}

__host__ __device__ __forceinline__ void threefry2x32_fn(
    uint32_t k0, uint32_t k1, uint32_t x0, uint32_t x1,
    uint32_t& o0, uint32_t& o1)
{
    uint32_t ks2 = k0 ^ k1 ^ 0x1BD11BDAu;
    x0 += k0; x1 += k1;
#define TFR(r) { x0 += x1; x1 = rotl32(x1, r); x1 ^= x0; }
    TFR(13) TFR(15) TFR(26) TFR(6)   x0 += k1;  x1 += ks2 + 1u;
    TFR(17) TFR(29) TFR(16) TFR(24)  x0 += ks2; x1 += k0  + 2u;
    TFR(13) TFR(15) TFR(26) TFR(6)   x0 += k0;  x1 += k1  + 3u;
    TFR(17) TFR(29) TFR(16) TFR(24)  x0 += k1;  x1 += ks2 + 4u;
    TFR(13) TFR(15) TFR(26) TFR(6)   x0 += ks2; x1 += k0  + 5u;
#undef TFR
    o0 = x0; o1 = x1;
}

// ---------------- edge dtype detection ----------------
__global__ void k_detect(const int* __restrict__ ei32)
{
    if (threadIdx.x == 0 && blockIdx.x == 0) {
        int w = 1;
        #pragma unroll 1
        for (int i = 0; i < 64; i++)
            if (ei32[2 * i + 1] != 0) { w = 0; break; }
        g_w64 = w;
    }
}

__device__ __forceinline__ void edge_endpoints(const int* __restrict__ ei32,
                                               int e, int& s, int& d)
{
    if (e >= E_RAW) { s = d = e - E_RAW; return; }
    if (g_w64) { s = ei32[2 * e]; d = ei32[2 * (E_RAW + e)]; }
    else       { s = ei32[e];     d = ei32[E_RAW + e]; }
}

// ---------------- CSR build ----------------
__global__ void k_zero()
{
    int i = blockIdx.x * blockDim.x + threadIdx.x;
    if (i < N_NODES) { g_deg[i] = 0; g_cur[i] = 0; }
}

__global__ void k_count(const int* __restrict__ ei32)
{
    int e = blockIdx.x * blockDim.x + threadIdx.x;
    if (e >= E_TOT) return;
    int sn, dn; edge_endpoints(ei32, e, sn, dn);
    atomicAdd(&g_deg[dn], 1);
}

#define SCAN_CHUNKS ((N_NODES + 1023) / 1024)
__global__ void k_scan()
{
    __shared__ int sh[1024];
    __shared__ int carry;
    int tid = threadIdx.x;
    if (tid == 0) carry = 0;
    __syncthreads();
    for (int c = 0; c < SCAN_CHUNKS; c++) {
        int i = c * 1024 + tid;
        int v = (i < N_NODES) ? g_deg[i] : 0;
        sh[tid] = v;
        __syncthreads();
        for (int off = 1; off < 1024; off <<= 1) {
            int t = (tid >= off) ? sh[tid - off] : 0;
            __syncthreads();
            sh[tid] += t;
            __syncthreads();
        }
        if (i < N_NODES) g_rowptr[i] = carry + sh[tid] - v;
        __syncthreads();
        if (tid == 0) carry += sh[1023];
        __syncthreads();
    }
    if (tid == 0) g_rowptr[N_NODES] = carry;
}

__global__ void k_fill(const int* __restrict__ ei32)
{
    int e = blockIdx.x * blockDim.x + threadIdx.x;
    if (e >= E_TOT) return;
    int sn, dn; edge_endpoints(ei32, e, sn, dn);
    int pos = atomicAdd(&g_cur[dn], 1);
    g_csrc[g_rowptr[dn] + pos] = sn;
}

// ---------------- fused dropout + (bias) + ELU ----------------
__global__ void k_dropelu(const float* __restrict__ in,
                          const float* __restrict__ bias,
                          int internal, uint32_t k0, uint32_t k1)
{
    long i = (long)blockIdx.x * blockDim.x + threadIdx.x;
    if (i >= TOTAL) return;
    float v;
    if (internal) v = g_out1[i] + bias[i & (DIM - 1)];
    else          v = in[i];

    uint32_t o0, o1;
    threefry2x32_fn(k0, k1, 0u, (uint32_t)i, o0, o1);
    uint32_t bits = o0 ^ o1;
    float u = __uint_as_float((bits >> 9) | 0x3f800000u) - 1.0f;

    v = (u < 0.8f) ? v * 1.25f : 0.0f;
    g_h[i] = (v > 0.0f) ? v : expm1f(v);
}

// ---------------- SGEMM: g_xp = g_h (Mx512) @ B (512x512) ----------------
// 128x128 tile, BK=16, double buffered, 8x8 micro-tile, 256 threads.
__global__ __launch_bounds__(256, 2) void k_sgemm(const float* __restrict__ B, int M)
{
    __shared__ float As[2][16][132];
    __shared__ float Bs[2][16][128];

    int tid = threadIdx.x;
    int tx = tid & 15, ty = tid >> 4;
    int rowBase = blockIdx.y * 128, colBase = blockIdx.x * 128;

    float4 aReg[2], bReg[2];

    // ---- load stage 0 directly to smem ----
    #pragma unroll
    for (int u = 0; u < 2; u++) {
        int idx = tid + u * 256;
        int r = idx >> 2, q = idx & 3;
        int gr = rowBase + r;
        float4 a = make_float4(0.f, 0.f, 0.f, 0.f);
        if (gr < M) a = *(const float4*)&g_h[(long)gr * DIM + q * 4];
        As[0][q * 4 + 0][r] = a.x;
        As[0][q * 4 + 1][r] = a.y;
        As[0][q * 4 + 2][r] = a.z;
        As[0][q * 4 + 3][r] = a.w;
        int kr = idx >> 5, c = (idx & 31) * 4;
        *(float4*)&Bs[0][kr][c] = *(const float4*)&B[(long)kr * DIM + colBase + c];
    }
    __syncthreads();

    float acc[8][8] = {};
    int buf = 0;

    for (int k0 = 0; k0 < DIM; k0 += 16) {
        int kNext = k0 + 16;
        if (kNext < DIM) {
            #pragma unroll
            for (int u = 0; u < 2; u++) {
                int idx = tid + u * 256;
                int r = idx >> 2, q = idx & 3;
                int gr = rowBase + r;
                aReg[u] = make_float4(0.f, 0.f, 0.f, 0.f);
                if (gr < M) aReg[u] = *(const float4*)&g_h[(long)gr * DIM + kNext + q * 4];
                int kr = idx >> 5, c = (idx & 31) * 4;
                bReg[u] = *(const float4*)&B[(long)(kNext + kr) * DIM + colBase + c];
            }
        }

        #pragma unroll
        for (int kk = 0; kk < 16; kk++) {
            float4 a0 = *(const float4*)&As[buf][kk][ty * 8];
            float4 a1 = *(const float4*)&As[buf][kk][ty * 8 + 4];
            float4 b0 = *(const float4*)&Bs[buf][kk][tx * 4];
            float4 b1 = *(const float4*)&Bs[buf][kk][tx * 4 + 64];
            float av[8] = { a0.x, a0.y, a0.z, a0.w, a1.x, a1.y, a1.z, a1.w };
            float bv[8] = { b0.x, b0.y, b0.z, b0.w, b1.x, b1.y, b1.z, b1.w };
            #pragma unroll
            for (int i = 0; i < 8; i++)
                #pragma unroll
                for (int j = 0; j < 8; j++)
                    acc[i][j] = fmaf(av[i], bv[j], acc[i][j]);
        }

        if (kNext < DIM) {
            int nb = buf ^ 1;
            #pragma unroll
            for (int u = 0; u < 2; u++) {
                int idx = tid + u * 256;
                int r = idx >> 2, q = idx & 3;
                As[nb][q * 4 + 0][r] = aReg[u].x;
                As[nb][q * 4 + 1][r] = aReg[u].y;
                As[nb][q * 4 + 2][r] = aReg[u].z;
                As[nb][q * 4 + 3][r] = aReg[u].w;
                int kr = idx >> 5, c = (idx & 31) * 4;
                *(float4*)&Bs[nb][kr][c] = bReg[u];
            }
            __syncthreads();
            buf = nb;
        }
    }

    #pragma unroll
    for (int i = 0; i < 8; i++) {
        int gr = rowBase + ty * 8 + i;
        if (gr < M) {
            float4 v0 = make_float4(acc[i][0], acc[i][1], acc[i][2], acc[i][3]);
            float4 v1 = make_float4(acc[i][4], acc[i][5], acc[i][6], acc[i][7]);
            *(float4*)&g_xp[(long)gr * DIM + colBase + tx * 4]      = v0;
            *(float4*)&g_xp[(long)gr * DIM + colBase + tx * 4 + 64] = v1;
        }
    }
}

// ---------------- per-(node,head) attention dot products ----------------
__global__ void k_attdot(const float* __restrict__ asrc, const float* __restrict__ adst)
{
    int n = blockIdx.x;
    int h = threadIdx.x >> 5;
    int lane = threadIdx.x & 31;
    const float* row = g_xp + (long)n * DIM + h * CH;
    float v0 = row[lane], v1 = row[lane + 32];
    float s = v0 * asrc[h * CH + lane] + v1 * asrc[h * CH + lane + 32];
    float d = v0 * adst[h * CH + lane] + v1 * adst[h * CH + lane + 32];
    #pragma unroll
    for (int o = 16; o; o >>= 1) {
        s += __shfl_xor_sync(0xFFFFFFFFu, s, o);
        d += __shfl_xor_sync(0xFFFFFFFFu, d, o);
    }
    if (lane == 0) { g_as[n * HEADS + h] = s; g_ad[n * HEADS + h] = d; }
}

// ---------------- fused softmax + message aggregation ----------------
// One block per dst node; warp h handles head h. CSR in-edges. No atomics.
__global__ void k_aggr()
{
    int dn = blockIdx.x;
    int h = threadIdx.x >> 5;
    int lane = threadIdx.x & 31;
    int row0 = g_rowptr[dn];
    int deg  = g_rowptr[dn + 1] - row0;
    float advl = g_ad[dn * HEADS + h];

    // pass 1: segment max
    float mx = -3.4e38f;
    for (int j = lane; j < deg; j += 32) {
        int sn = g_csrc[row0 + j];
        float e = g_as[sn * HEADS + h] + advl;
        e = (e > 0.0f) ? e : 0.2f * e;
        mx = fmaxf(mx, e);
    }
    #pragma unroll
    for (int o = 16; o; o >>= 1)
        mx = fmaxf(mx, __shfl_xor_sync(0xFFFFFFFFu, mx, o));

    // pass 2: segment sum of exp
    float sm = 0.0f;
    for (int j = lane; j < deg; j += 32) {
        int sn = g_csrc[row0 + j];
        float e = g_as[sn * HEADS + h] + advl;
        e = (e > 0.0f) ? e : 0.2f * e;
        sm += expf(e - mx);
    }
    #pragma unroll
    for (int o = 16; o; o >>= 1)
        sm += __shfl_xor_sync(0xFFFFFFFFu, sm, o);
    float inv = 1.0f / (sm + 1e-16f);

    // pass 3: alpha-weighted gather-accumulate (64 channels = float2/lane)
    float ax = 0.0f, ay = 0.0f;
    for (int base = 0; base < deg; base += 32) {
        int j = base + lane;
        float alpha = 0.0f;
        int sn = 0;
        if (j < deg) {
            sn = g_csrc[row0 + j];
            float e = g_as[sn * HEADS + h] + advl;
            e = (e > 0.0f) ? e : 0.2f * e;
            alpha = expf(e - mx) * inv;
        }
        int cnt = min(32, deg - base);
        #pragma unroll 1
        for (int t = 0; t < cnt; t++) {
            float a  = __shfl_sync(0xFFFFFFFFu, alpha, t);
            int   sc = __shfl_sync(0xFFFFFFFFu, sn, t);
            float2 v = *(const float2*)&g_xp[(long)sc * DIM + h * CH + lane * 2];
            ax = fmaf(a, v.x, ax);
            ay = fmaf(a, v.y, ay);
        }
    }
    *(float2*)&g_out1[(long)dn * DIM + h * CH + lane * 2] = make_float2(ax, ay);
}

// ---------------- final: mean over heads + bias ----------------
__global__ void k_final(const float* __restrict__ b2, float* __restrict__ out)
{
    int i = blockIdx.x * blockDim.x + threadIdx.x;
    if (i >= N_NODES * CH) return;
    int n = i >> 6, c = i & 63;
    float acc = 0.0f;
    #pragma unroll
    for (int h = 0; h < HEADS; h++)
        acc += g_out1[(long)n * DIM + h * CH + c];
    out[i] = acc * 0.125f + b2[c];
}

// ---------------- host orchestration ----------------
extern "C" void kernel_launch(void* const* d_in, const int* in_sizes, int n_in,
                              void* d_out, int out_size)
{
    const float* x   = (const float*)d_in[0];
    const int*   ei  = (const int*)d_in[1];
    const float* W1  = (const float*)d_in[2];
    const float* as1 = (const float*)d_in[3];
    const float* ad1 = (const float*)d_in[4];
    const float* b1  = (const float*)d_in[5];
    const float* W2  = (const float*)d_in[6];
    const float* as2 = (const float*)d_in[7];
    const float* ad2 = (const float*)d_in[8];
    const float* b2  = (const float*)d_in[9];
    float*       out = (float*)d_out;

    // key(42) = (0,42); partitionable split: key_j = threefry2x32(key, 0, j)
    uint32_t k1a, k1b, k2a, k2b;
    threefry2x32_fn(0u, 42u, 0u, 0u, k1a, k1b);
    threefry2x32_fn(0u, 42u, 0u, 1u, k2a, k2b);

    const int elemBlocks = (int)((TOTAL + 255) / 256);
    const int edgeBlocks = (E_TOT + 255) / 256;
    const int nodeBlocks = (N_NODES + 255) / 256;
    dim3 gemmGrid(DIM / 128, (N_NODES + 127) / 128);

    // ---- CSR build (shared by both layers) ----
    k_detect<<<1, 32>>>(ei);
    k_zero<<<nodeBlocks, 256>>>();
    k_count<<<edgeBlocks, 256>>>(ei);
    k_scan<<<1, 1024>>>();
    k_fill<<<edgeBlocks, 256>>>(ei);

    // ---- layer 1 ----
    k_dropelu<<<elemBlocks, 256>>>(x, nullptr, 0, k1a, k1b);
    k_sgemm<<<gemmGrid, 256>>>(W1, N_NODES);
    k_attdot<<<N_NODES, 256>>>(as1, ad1);
    k_aggr<<<N_NODES, 256>>>();

    // ---- layer 2 ----
    k_dropelu<<<elemBlocks, 256>>>(nullptr, b1, 1, k2a, k2b);
    k_sgemm<<<gemmGrid, 256>>>(W2, N_NODES);
    k_attdot<<<N_NODES, 256>>>(as2, ad2);
    k_aggr<<<N_NODES, 256>>>();

    k_final<<<(N_NODES * CH + 255) / 256, 256>>>(b2, out);
}

// round 6
// speedup vs baseline: 3.0061x; 1.4906x over previous
#include <cuda_runtime.h>
#include <cuda_bf16.h>
#include <cstdint>

#define N_NODES 30000
#define E_RAW   480000
#define E_TOT   (E_RAW + N_NODES)
#define DIM     512
#define HEADS   8
#define CH      64
#define NH      (N_NODES * HEADS)
#define TOTAL   ((long)N_NODES * DIM)

// ---------------- scratch (device globals; no allocations) ----------------
__device__ __nv_bfloat16 g_ahi[(size_t)N_NODES * DIM];
__device__ __nv_bfloat16 g_alo[(size_t)N_NODES * DIM];
__device__ __nv_bfloat16 g_bhi[(size_t)DIM * DIM];
__device__ __nv_bfloat16 g_blo[(size_t)DIM * DIM];
__device__ float g_xp  [(size_t)N_NODES * DIM];
__device__ float g_out1[(size_t)N_NODES * DIM];
__device__ float g_as  [NH];
__device__ float g_ad  [NH];
__device__ int   g_deg [N_NODES];
__device__ int   g_cur [N_NODES];
__device__ int   g_rowptr[N_NODES + 1];
__device__ int   g_csrc[E_TOT];
__device__ int   g_w64;
#define SCAN_BLOCKS ((N_NODES + 1023) / 1024)
__device__ int   g_bsum[SCAN_BLOCKS];

// ---------------- PTX helpers (baseline ISA only; no 'a' features) ----------------
__device__ __forceinline__ uint32_t smem_u32(const void* p) {
    uint32_t a;
    asm("{ .reg .u64 t; cvta.to.shared.u64 t, %1; cvt.u32.u64 %0, t; }" : "=r"(a) : "l"(p));
    return a;
}
#define STS128(a, r0, r1, r2, r3) \
    asm volatile("st.shared.v4.b32 [%0], {%1, %2, %3, %4};" :: "r"(a), "r"(r0), "r"(r1), "r"(r2), "r"(r3) : "memory")

__device__ __forceinline__ void ldsm_x4(uint32_t* r, uint32_t addr) {
    asm volatile("ldmatrix.sync.aligned.m8n8.x4.shared.b16 {%0,%1,%2,%3}, [%4];"
                 : "=r"(r[0]), "=r"(r[1]), "=r"(r[2]), "=r"(r[3]) : "r"(addr));
}
__device__ __forceinline__ void mma_16816(float* d, const uint32_t* a, const uint32_t* b) {
    asm volatile("mma.sync.aligned.m16n8k16.row.col.f32.bf16.bf16.f32 "
                 "{%0,%1,%2,%3}, {%4,%5,%6,%7}, {%8,%9}, {%0,%1,%2,%3};"
                 : "+f"(d[0]), "+f"(d[1]), "+f"(d[2]), "+f"(d[3])
                 : "r"(a[0]), "r"(a[1]), "r"(a[2]), "r"(a[3]), "r"(b[0]), "r"(b[1]));
}

// ---------------- threefry2x32 (bit-exact JAX, partitionable) ----------------
__host__ __device__ __forceinline__ uint32_t rotl32(uint32_t v, int r) {
    return (v << r) | (v >> (32 - r));
}
__host__ __device__ __forceinline__ void threefry2x32_fn(
    uint32_t k0, uint32_t k1, uint32_t x0, uint32_t x1, uint32_t& o0, uint32_t& o1)
{
    uint32_t ks2 = k0 ^ k1 ^ 0x1BD11BDAu;
    x0 += k0; x1 += k1;
#define TFR(r) { x0 += x1; x1 = rotl32(x1, r); x1 ^= x0; }
    TFR(13) TFR(15) TFR(26) TFR(6)   x0 += k1;  x1 += ks2 + 1u;
    TFR(17) TFR(29) TFR(16) TFR(24)  x0 += ks2; x1 += k0  + 2u;
    TFR(13) TFR(15) TFR(26) TFR(6)   x0 += k0;  x1 += k1  + 3u;
    TFR(17) TFR(29) TFR(16) TFR(24)  x0 += k1;  x1 += ks2 + 4u;
    TFR(13) TFR(15) TFR(26) TFR(6)   x0 += ks2; x1 += k0  + 5u;
#undef TFR
    o0 = x0; o1 = x1;
}

// ---------------- edge dtype detection ----------------
__global__ void k_detect(const int* __restrict__ ei32)
{
    if (threadIdx.x == 0 && blockIdx.x == 0) {
        int w = 1;
        #pragma unroll 1
        for (int i = 0; i < 64; i++)
            if (ei32[2 * i + 1] != 0) { w = 0; break; }
        g_w64 = w;
    }
}
__device__ __forceinline__ void edge_endpoints(const int* __restrict__ ei32,
                                               int e, int& s, int& d)
{
    if (e >= E_RAW) { s = d = e - E_RAW; return; }
    if (g_w64) { s = ei32[2 * e]; d = ei32[2 * (E_RAW + e)]; }
    else       { s = ei32[e];     d = ei32[E_RAW + e]; }
}

// ---------------- CSR build ----------------
__global__ void k_zero()
{
    int i = blockIdx.x * blockDim.x + threadIdx.x;
    if (i < N_NODES) { g_deg[i] = 0; g_cur[i] = 0; }
}
__global__ void k_count(const int* __restrict__ ei32)
{
    int e = blockIdx.x * blockDim.x + threadIdx.x;
    if (e >= E_TOT) return;
    int sn, dn; edge_endpoints(ei32, e, sn, dn);
    atomicAdd(&g_deg[dn], 1);
}
__global__ void k_scan1()
{
    __shared__ int sh[1024];
    int tid = threadIdx.x;
    int i = blockIdx.x * 1024 + tid;
    int v = (i < N_NODES) ? g_deg[i] : 0;
    sh[tid] = v;
    __syncthreads();
    for (int off = 1; off < 1024; off <<= 1) {
        int t = (tid >= off) ? sh[tid - off] : 0;
        __syncthreads();
        sh[tid] += t;
        __syncthreads();
    }
    if (i < N_NODES) g_rowptr[i] = sh[tid] - v;
    if (tid == 1023) g_bsum[blockIdx.x] = sh[1023];
}
__global__ void k_scan2()
{
    int tid = threadIdx.x;
    int v = (tid < SCAN_BLOCKS) ? g_bsum[tid] : 0;
    int incl = v;
    #pragma unroll
    for (int off = 1; off < 32; off <<= 1) {
        int t = __shfl_up_sync(0xFFFFFFFFu, incl, off);
        if (tid >= off) incl += t;
    }
    if (tid < SCAN_BLOCKS) g_bsum[tid] = incl - v;
    if (tid == 31) g_rowptr[N_NODES] = incl;
}
__global__ void k_scan3()
{
    int i = blockIdx.x * blockDim.x + threadIdx.x;
    if (i < N_NODES) g_rowptr[i] += g_bsum[i >> 10];
}
__global__ void k_fill(const int* __restrict__ ei32)
{
    int e = blockIdx.x * blockDim.x + threadIdx.x;
    if (e >= E_TOT) return;
    int sn, dn; edge_endpoints(ei32, e, sn, dn);
    int pos = atomicAdd(&g_cur[dn], 1);
    g_csrc[g_rowptr[dn] + pos] = sn;
}

// ---------------- fused dropout + (bias) + ELU -> bf16 hi/lo split ----------------
__global__ void k_dropelu(const float* __restrict__ in,
                          const float* __restrict__ bias,
                          int internal, uint32_t k0, uint32_t k1)
{
    long i = (long)blockIdx.x * blockDim.x + threadIdx.x;
    if (i >= TOTAL) return;
    float v;
    if (internal) v = g_out1[i] + bias[i & (DIM - 1)];
    else          v = in[i];

    uint32_t o0, o1;
    threefry2x32_fn(k0, k1, 0u, (uint32_t)i, o0, o1);
    uint32_t bits = o0 ^ o1;
    float u = __uint_as_float((bits >> 9) | 0x3f800000u) - 1.0f;

    v = (u < 0.8f) ? v * 1.25f : 0.0f;
    v = (v > 0.0f) ? v : expm1f(v);

    __nv_bfloat16 hi = __float2bfloat16(v);
    __nv_bfloat16 lo = __float2bfloat16(v - __bfloat162float(hi));
    g_ahi[i] = hi;
    g_alo[i] = lo;
}

// ---------------- W -> transposed bf16 hi/lo split: B[n][k] = W[k][n] ----------------
__global__ void k_wsplit(const float* __restrict__ W)
{
    int i = blockIdx.x * blockDim.x + threadIdx.x;
    if (i >= DIM * DIM) return;
    int k = i >> 9, n = i & (DIM - 1);
    float w = W[i];
    __nv_bfloat16 hi = __float2bfloat16(w);
    __nv_bfloat16 lo = __float2bfloat16(w - __bfloat162float(hi));
    g_bhi[n * DIM + k] = hi;
    g_blo[n * DIM + k] = lo;
}

// ---------------- HMMA bf16-split GEMM + fused attention dots ----------------
// C = (Ahi+Alo) @ (Bhi+Blo)^T dropping lo*lo. Block 128x128, BK=32,
// 8 warps (4m x 2n), warp tile 32x64, mma.m16n8k16, ldmatrix operands.
// SMEM: 2 stages x 4 arrays x 128 rows x 80B (40 bf16, 16B-aligned stride).
#define ROWB   80
#define ARRB   10240              // 128 * 80
#define STAGEB 40960              // 4 * ARRB
__global__ __launch_bounds__(256, 1) void k_mm(
    const float* __restrict__ asrc, const float* __restrict__ adst, int M)
{
    extern __shared__ char smem[];
    const uint32_t smBase = smem_u32(smem);
    const int tid = threadIdx.x;
    const int lane = tid & 31, wid = tid >> 5;
    const int wm = wid & 3, wn = wid >> 2;
    const int rowBase = blockIdx.y * 128, colBase = blockIdx.x * 128;

    float acc[2][8][4] = {};
    uint4 st[8];

    auto load_stage = [&](int kb) {
        #pragma unroll
        for (int a = 0; a < 4; a++) {
            #pragma unroll
            for (int u = 0; u < 2; u++) {
                int cid = tid + u * 256;
                int row = cid >> 2, kc = cid & 3;
                const __nv_bfloat16* src;
                long gr;
                bool ok = true;
                if (a == 0)      { src = g_ahi; gr = rowBase + row; ok = (gr < M); }
                else if (a == 1) { src = g_alo; gr = rowBase + row; ok = (gr < M); }
                else if (a == 2) { src = g_bhi; gr = colBase + row; }
                else             { src = g_blo; gr = colBase + row; }
                st[a * 2 + u] = ok ? *(const uint4*)(src + gr * DIM + kb * 32 + kc * 8)
                                   : make_uint4(0u, 0u, 0u, 0u);
            }
        }
    };
    auto store_stage = [&](int buf) {
        #pragma unroll
        for (int a = 0; a < 4; a++) {
            #pragma unroll
            for (int u = 0; u < 2; u++) {
                int cid = tid + u * 256;
                int row = cid >> 2, kc = cid & 3;
                uint32_t addr = smBase + buf * STAGEB + a * ARRB + row * ROWB + kc * 16;
                uint4 v = st[a * 2 + u];
                STS128(addr, v.x, v.y, v.z, v.w);
            }
        }
    };

    load_stage(0);
    store_stage(0);
    __syncthreads();

    const int li = lane & 7, grp = lane >> 3;
    const int aRow = li + (grp & 1) * 8;      // + chunk (grp>>1)
    const int bRow = li + (grp >> 1) * 8;     // + chunk (grp&1)

    #pragma unroll 1
    for (int kb = 0; kb < 16; kb++) {
        if (kb < 15) load_stage(kb + 1);

        uint32_t sA = smBase + (kb & 1) * STAGEB;
        #pragma unroll
        for (int ks = 0; ks < 2; ks++) {
            uint32_t ahi[2][4], alo[2][4], bhi[4][4], blo[4][4];
            int aChunk = ks * 2 + (grp >> 1);
            int bChunk = ks * 2 + (grp & 1);
            #pragma unroll
            for (int mt = 0; mt < 2; mt++) {
                uint32_t off = (uint32_t)(wm * 32 + mt * 16 + aRow) * ROWB + aChunk * 16;
                ldsm_x4(ahi[mt], sA + off);
                ldsm_x4(alo[mt], sA + ARRB + off);
            }
            #pragma unroll
            for (int p = 0; p < 4; p++) {
                uint32_t off = (uint32_t)(wn * 64 + p * 16 + bRow) * ROWB + bChunk * 16;
                ldsm_x4(bhi[p], sA + 2 * ARRB + off);
                ldsm_x4(blo[p], sA + 3 * ARRB + off);
            }
            #pragma unroll
            for (int mt = 0; mt < 2; mt++) {
                #pragma unroll
                for (int nt = 0; nt < 8; nt++) {
                    const uint32_t* bh = &bhi[nt >> 1][(nt & 1) * 2];
                    const uint32_t* bl = &blo[nt >> 1][(nt & 1) * 2];
                    float* d = acc[mt][nt];
                    mma_16816(d, ahi[mt], bh);
                    mma_16816(d, ahi[mt], bl);
                    mma_16816(d, alo[mt], bh);
                }
            }
        }

        if (kb < 15) {
            __syncthreads();
            store_stage((kb + 1) & 1);
            __syncthreads();
        }
    }

    // ---- epilogue: store C + fused attention dots ----
    const int head = blockIdx.x * 2 + wn;
    const float* av = asrc + head * CH;
    const float* dv = adst + head * CH;
    const int q = lane >> 2, qt = lane & 3;

    #pragma unroll
    for (int mt = 0; mt < 2; mt++) {
        int r0 = rowBase + wm * 32 + mt * 16 + q;
        int r1 = r0 + 8;
        float s0 = 0.f, s1 = 0.f, t0 = 0.f, t1 = 0.f;
        #pragma unroll
        for (int nt = 0; nt < 8; nt++) {
            int lc = nt * 8 + qt * 2;
            float a0v = av[lc], a1v = av[lc + 1];
            float d0v = dv[lc], d1v = dv[lc + 1];
            float* d = acc[mt][nt];
            s0 += d[0] * a0v + d[1] * a1v;  t0 += d[0] * d0v + d[1] * d1v;
            s1 += d[2] * a0v + d[3] * a1v;  t1 += d[2] * d0v + d[3] * d1v;
            long cb = colBase + wn * 64 + lc;
            if (r0 < M) *(float2*)&g_xp[(long)r0 * DIM + cb] = make_float2(d[0], d[1]);
            if (r1 < M) *(float2*)&g_xp[(long)r1 * DIM + cb] = make_float2(d[2], d[3]);
        }
        #pragma unroll
        for (int o = 1; o < 4; o <<= 1) {
            s0 += __shfl_xor_sync(0xFFFFFFFFu, s0, o);
            s1 += __shfl_xor_sync(0xFFFFFFFFu, s1, o);
            t0 += __shfl_xor_sync(0xFFFFFFFFu, t0, o);
            t1 += __shfl_xor_sync(0xFFFFFFFFu, t1, o);
        }
        if (qt == 0) {
            if (r0 < M) { g_as[r0 * HEADS + head] = s0; g_ad[r0 * HEADS + head] = t0; }
            if (r1 < M) { g_as[r1 * HEADS + head] = s1; g_ad[r1 * HEADS + head] = t1; }
        }
    }
}

// ---------------- fused online softmax + message aggregation ----------------
__global__ void k_aggr()
{
    int dn = blockIdx.x;
    int h = threadIdx.x >> 5;
    int lane = threadIdx.x & 31;
    int row0 = g_rowptr[dn];
    int deg  = g_rowptr[dn + 1] - row0;
    float advl = g_ad[dn * HEADS + h];

    float mx = -3.4e38f, sm = 0.0f;
    for (int j = lane; j < deg; j += 32) {
        int sn = g_csrc[row0 + j];
        float e = g_as[sn * HEADS + h] + advl;
        e = (e > 0.0f) ? e : 0.2f * e;
        if (e > mx) { sm = sm * expf(mx - e) + 1.0f; mx = e; }
        else        { sm += expf(e - mx); }
    }
    #pragma unroll
    for (int o = 16; o; o >>= 1) {
        float mo = __shfl_xor_sync(0xFFFFFFFFu, mx, o);
        float so = __shfl_xor_sync(0xFFFFFFFFu, sm, o);
        float M2 = fmaxf(mx, mo);
        sm = sm * expf(mx - M2) + so * expf(mo - M2);
        mx = M2;
    }
    float inv = 1.0f / (sm + 1e-16f);

    float ax = 0.0f, ay = 0.0f;
    for (int base = 0; base < deg; base += 32) {
        int j = base + lane;
        float alpha = 0.0f;
        int sn = 0;
        if (j < deg) {
            sn = g_csrc[row0 + j];
            float e = g_as[sn * HEADS + h] + advl;
            e = (e > 0.0f) ? e : 0.2f * e;
            alpha = expf(e - mx) * inv;
        }
        int cnt = min(32, deg - base);
        #pragma unroll 1
        for (int t = 0; t < cnt; t++) {
            float a  = __shfl_sync(0xFFFFFFFFu, alpha, t);
            int   sc = __shfl_sync(0xFFFFFFFFu, sn, t);
            float2 v = *(const float2*)&g_xp[(long)sc * DIM + h * CH + lane * 2];
            ax = fmaf(a, v.x, ax);
            ay = fmaf(a, v.y, ay);
        }
    }
    *(float2*)&g_out1[(long)dn * DIM + h * CH + lane * 2] = make_float2(ax, ay);
}

// ---------------- final: mean over heads + bias ----------------
__global__ void k_final(const float* __restrict__ b2, float* __restrict__ out)
{
    int i = blockIdx.x * blockDim.x + threadIdx.x;
    if (i >= N_NODES * CH) return;
    int n = i >> 6, c = i & 63;
    float acc = 0.0f;
    #pragma unroll
    for (int h = 0; h < HEADS; h++)
        acc += g_out1[(long)n * DIM + h * CH + c];
    out[i] = acc * 0.125f + b2[c];
}

// ---------------- host orchestration ----------------
extern "C" void kernel_launch(void* const* d_in, const int* in_sizes, int n_in,
                              void* d_out, int out_size)
{
    const float* x   = (const float*)d_in[0];
    const int*   ei  = (const int*)d_in[1];
    const float* W1  = (const float*)d_in[2];
    const float* as1 = (const float*)d_in[3];
    const float* ad1 = (const float*)d_in[4];
    const float* b1  = (const float*)d_in[5];
    const float* W2  = (const float*)d_in[6];
    const float* as2 = (const float*)d_in[7];
    const float* ad2 = (const float*)d_in[8];
    const float* b2  = (const float*)d_in[9];
    float*       out = (float*)d_out;

    uint32_t k1a, k1b, k2a, k2b;
    threefry2x32_fn(0u, 42u, 0u, 0u, k1a, k1b);
    threefry2x32_fn(0u, 42u, 0u, 1u, k2a, k2b);

    const int SMEM_MM = 2 * STAGEB;   // 81920
    static int attrSet = 0;
    if (!attrSet) {
        cudaFuncSetAttribute(k_mm, cudaFuncAttributeMaxDynamicSharedMemorySize, SMEM_MM);
        attrSet = 1;
    }

    const int elemBlocks = (int)((TOTAL + 255) / 256);
    const int edgeBlocks = (E_TOT + 255) / 256;
    const int nodeBlocks = (N_NODES + 255) / 256;
    const int wBlocks    = (DIM * DIM + 255) / 256;
    dim3 gemmGrid(DIM / 128, (N_NODES + 127) / 128);

    // ---- CSR build (shared by both layers) ----
    k_detect<<<1, 32>>>(ei);
    k_zero<<<nodeBlocks, 256>>>();
    k_count<<<edgeBlocks, 256>>>(ei);
    k_scan1<<<SCAN_BLOCKS, 1024>>>();
    k_scan2<<<1, 32>>>();
    k_scan3<<<nodeBlocks, 256>>>();
    k_fill<<<edgeBlocks, 256>>>(ei);

    // ---- layer 1 ----
    k_wsplit<<<wBlocks, 256>>>(W1);
    k_dropelu<<<elemBlocks, 256>>>(x, nullptr, 0, k1a, k1b);
    k_mm<<<gemmGrid, 256, SMEM_MM>>>(as1, ad1, N_NODES);
    k_aggr<<<N_NODES, 256>>>();

    // ---- layer 2 ----
    k_wsplit<<<wBlocks, 256>>>(W2);
    k_dropelu<<<elemBlocks, 256>>>(nullptr, b1, 1, k2a, k2b);
    k_mm<<<gemmGrid, 256, SMEM_MM>>>(as2, ad2, N_NODES);
    k_aggr<<<N_NODES, 256>>>();

    k_final<<<(N_NODES * CH + 255) / 256, 256>>>(b2, out);
}

// round 7
// speedup vs baseline: 3.4671x; 1.1534x over previous
#include <cuda_runtime.h>
#include <cuda_bf16.h>
#include <cstdint>

#define N_NODES 30000
#define E_RAW   480000
#define E_TOT   (E_RAW + N_NODES)
#define DIM     512
#define HEADS   8
#define CH      64
#define NH      (N_NODES * HEADS)
#define TOTAL   ((long)N_NODES * DIM)

// ---------------- scratch (device globals; no allocations) ----------------
__device__ __nv_bfloat16 g_ahi[(size_t)N_NODES * DIM];
__device__ __nv_bfloat16 g_alo[(size_t)N_NODES * DIM];
__device__ __nv_bfloat16 g_bhi[(size_t)DIM * DIM];
__device__ __nv_bfloat16 g_blo[(size_t)DIM * DIM];
__device__ float g_xp  [(size_t)N_NODES * DIM];
__device__ float g_as  [NH];
__device__ float g_ad  [NH];
__device__ int   g_deg [N_NODES];
__device__ int   g_cur [N_NODES];
__device__ int   g_rowptr[N_NODES + 1];
__device__ int   g_csrc[E_TOT];
__device__ int   g_w64;
#define SCAN_BLOCKS ((N_NODES + 1023) / 1024)
__device__ int   g_bsum[SCAN_BLOCKS];

// ---------------- PTX helpers (baseline ISA only; no 'a' features) ----------------
__device__ __forceinline__ uint32_t smem_u32(const void* p) {
    uint32_t a;
    asm("{ .reg .u64 t; cvta.to.shared.u64 t, %1; cvt.u32.u64 %0, t; }" : "=r"(a) : "l"(p));
    return a;
}
__device__ __forceinline__ void cp_async16(uint32_t saddr, const void* gaddr, int srcBytes) {
    asm volatile("cp.async.ca.shared.global [%0], [%1], 16, %2;"
                 :: "r"(saddr), "l"(gaddr), "r"(srcBytes) : "memory");
}
#define CP_COMMIT() asm volatile("cp.async.commit_group;" ::: "memory")
#define CP_WAIT2()  asm volatile("cp.async.wait_group 2;" ::: "memory")

__device__ __forceinline__ void ldsm_x4(uint32_t* r, uint32_t addr) {
    asm volatile("ldmatrix.sync.aligned.m8n8.x4.shared.b16 {%0,%1,%2,%3}, [%4];"
                 : "=r"(r[0]), "=r"(r[1]), "=r"(r[2]), "=r"(r[3]) : "r"(addr));
}
__device__ __forceinline__ void mma_16816(float* d, const uint32_t* a, const uint32_t* b) {
    asm volatile("mma.sync.aligned.m16n8k16.row.col.f32.bf16.bf16.f32 "
                 "{%0,%1,%2,%3}, {%4,%5,%6,%7}, {%8,%9}, {%0,%1,%2,%3};"
                 : "+f"(d[0]), "+f"(d[1]), "+f"(d[2]), "+f"(d[3])
                 : "r"(a[0]), "r"(a[1]), "r"(a[2]), "r"(a[3]), "r"(b[0]), "r"(b[1]));
}

// ---------------- threefry2x32 (bit-exact JAX, partitionable) ----------------
__host__ __device__ __forceinline__ uint32_t rotl32(uint32_t v, int r) {
    return (v << r) | (v >> (32 - r));
}
__host__ __device__ __forceinline__ void threefry2x32_fn(
    uint32_t k0, uint32_t k1, uint32_t x0, uint32_t x1, uint32_t& o0, uint32_t& o1)
{
    uint32_t ks2 = k0 ^ k1 ^ 0x1BD11BDAu;
    x0 += k0; x1 += k1;
#define TFR(r) { x0 += x1; x1 = rotl32(x1, r); x1 ^= x0; }
    TFR(13) TFR(15) TFR(26) TFR(6)   x0 += k1;  x1 += ks2 + 1u;
    TFR(17) TFR(29) TFR(16) TFR(24)  x0 += ks2; x1 += k0  + 2u;
    TFR(13) TFR(15) TFR(26) TFR(6)   x0 += k0;  x1 += k1  + 3u;
    TFR(17) TFR(29) TFR(16) TFR(24)  x0 += k1;  x1 += ks2 + 4u;
    TFR(13) TFR(15) TFR(26) TFR(6)   x0 += ks2; x1 += k0  + 5u;
#undef TFR
    o0 = x0; o1 = x1;
}

__device__ __forceinline__ float drop_elu(float v, long idx, uint32_t k0, uint32_t k1)
{
    uint32_t o0, o1;
    threefry2x32_fn(k0, k1, 0u, (uint32_t)idx, o0, o1);
    float u = __uint_as_float((((o0 ^ o1)) >> 9) | 0x3f800000u) - 1.0f;
    v = (u < 0.8f) ? v * 1.25f : 0.0f;
    return (v > 0.0f) ? v : expm1f(v);
}

// ---------------- edge dtype detection ----------------
__global__ void k_detect(const int* __restrict__ ei32)
{
    if (threadIdx.x == 0 && blockIdx.x == 0) {
        int w = 1;
        #pragma unroll 1
        for (int i = 0; i < 64; i++)
            if (ei32[2 * i + 1] != 0) { w = 0; break; }
        g_w64 = w;
    }
}
__device__ __forceinline__ void edge_endpoints(const int* __restrict__ ei32,
                                               int e, int& s, int& d)
{
    if (e >= E_RAW) { s = d = e - E_RAW; return; }
    if (g_w64) { s = ei32[2 * e]; d = ei32[2 * (E_RAW + e)]; }
    else       { s = ei32[e];     d = ei32[E_RAW + e]; }
}

// ---------------- CSR build ----------------
__global__ void k_zero()
{
    int i = blockIdx.x * blockDim.x + threadIdx.x;
    if (i < N_NODES) { g_deg[i] = 0; g_cur[i] = 0; }
}
__global__ void k_count(const int* __restrict__ ei32)
{
    int e = blockIdx.x * blockDim.x + threadIdx.x;
    if (e >= E_TOT) return;
    int sn, dn; edge_endpoints(ei32, e, sn, dn);
    atomicAdd(&g_deg[dn], 1);
}
__global__ void k_scan1()
{
    __shared__ int sh[1024];
    int tid = threadIdx.x;
    int i = blockIdx.x * 1024 + tid;
    int v = (i < N_NODES) ? g_deg[i] : 0;
    sh[tid] = v;
    __syncthreads();
    for (int off = 1; off < 1024; off <<= 1) {
        int t = (tid >= off) ? sh[tid - off] : 0;
        __syncthreads();
        sh[tid] += t;
        __syncthreads();
    }
    if (i < N_NODES) g_rowptr[i] = sh[tid] - v;
    if (tid == 1023) g_bsum[blockIdx.x] = sh[1023];
}
__global__ void k_scan2()
{
    int tid = threadIdx.x;
    int v = (tid < SCAN_BLOCKS) ? g_bsum[tid] : 0;
    int incl = v;
    #pragma unroll
    for (int off = 1; off < 32; off <<= 1) {
        int t = __shfl_up_sync(0xFFFFFFFFu, incl, off);
        if (tid >= off) incl += t;
    }
    if (tid < SCAN_BLOCKS) g_bsum[tid] = incl - v;
    if (tid == 31) g_rowptr[N_NODES] = incl;
}
__global__ void k_scan3()
{
    int i = blockIdx.x * blockDim.x + threadIdx.x;
    if (i < N_NODES) g_rowptr[i] += g_bsum[i >> 10];
}
__global__ void k_fill(const int* __restrict__ ei32)
{
    int e = blockIdx.x * blockDim.x + threadIdx.x;
    if (e >= E_TOT) return;
    int sn, dn; edge_endpoints(ei32, e, sn, dn);
    int pos = atomicAdd(&g_cur[dn], 1);
    g_csrc[g_rowptr[dn] + pos] = sn;
}

// ---------------- layer-1 input: dropout + ELU -> bf16 hi/lo split ----------------
__global__ void k_dropelu(const float* __restrict__ in, uint32_t k0, uint32_t k1)
{
    long i = (long)blockIdx.x * blockDim.x + threadIdx.x;
    if (i >= TOTAL) return;
    float v = drop_elu(in[i], i, k0, k1);
    __nv_bfloat16 hi = __float2bfloat16(v);
    g_ahi[i] = hi;
    g_alo[i] = __float2bfloat16(v - __bfloat162float(hi));
}

// ---------------- W -> transposed bf16 hi/lo split: B[n][k] = W[k][n] ----------------
__global__ void k_wsplit(const float* __restrict__ W)
{
    int i = blockIdx.x * blockDim.x + threadIdx.x;
    if (i >= DIM * DIM) return;
    int k = i >> 9, n = i & (DIM - 1);
    float w = W[i];
    __nv_bfloat16 hi = __float2bfloat16(w);
    __nv_bfloat16 lo = __float2bfloat16(w - __bfloat162float(hi));
    g_bhi[n * DIM + k] = hi;
    g_blo[n * DIM + k] = lo;
}

// ---------------- HMMA bf16-split GEMM + fused attention dots ----------------
// C = (Ahi+Alo) @ (Bhi+Blo)^T dropping lo*lo. Block 128x128, BK=32,
// 8 warps (4m x 2n), warp tile 32x64, mma.m16n8k16, cp.async 4-stage pipeline.
#define ROWB   80
#define ARRB   10240              // 128 * 80
#define STAGEB 40960              // 4 * ARRB
#define STAGES 4
__global__ __launch_bounds__(256, 1) void k_mm(
    const float* __restrict__ asrc, const float* __restrict__ adst, int M)
{
    extern __shared__ char smem[];
    const uint32_t smBase = smem_u32(smem);
    const int tid = threadIdx.x;
    const int lane = tid & 31, wid = tid >> 5;
    const int wm = wid & 3, wn = wid >> 2;
    const int rowBase = blockIdx.y * 128, colBase = blockIdx.x * 128;

    float acc[2][8][4] = {};

    auto issue_stage = [&](int kb) {
        uint32_t base = smBase + (kb & 3) * STAGEB;
        #pragma unroll
        for (int q = 0; q < 8; q++) {
            int a = q >> 1;
            int cid = tid + (q & 1) * 256;      // 512 16B-chunks per array
            int row = cid >> 2, kc = cid & 3;
            const __nv_bfloat16* src;
            long gr;
            bool ok = true;
            if (a == 0)      { src = g_ahi; gr = rowBase + row; ok = (gr < M); }
            else if (a == 1) { src = g_alo; gr = rowBase + row; ok = (gr < M); }
            else if (a == 2) { src = g_bhi; gr = colBase + row; }
            else             { src = g_blo; gr = colBase + row; }
            uint32_t sa = base + a * ARRB + row * ROWB + kc * 16;
            cp_async16(sa, src + gr * DIM + kb * 32 + kc * 8, ok ? 16 : 0);
        }
        CP_COMMIT();
    };

    issue_stage(0);
    issue_stage(1);
    issue_stage(2);

    const int li = lane & 7, grp = lane >> 3;
    const int aRow = li + (grp & 1) * 8;
    const int bRow = li + (grp >> 1) * 8;

    #pragma unroll 1
    for (int kb = 0; kb < 16; kb++) {
        CP_WAIT2();
        __syncthreads();
        if (kb + 3 < 16) issue_stage(kb + 3);
        else CP_COMMIT();                        // empty group keeps wait arithmetic exact

        uint32_t sA = smBase + (kb & 3) * STAGEB;
        #pragma unroll
        for (int ks = 0; ks < 2; ks++) {
            uint32_t ahi[2][4], alo[2][4], bhi[4][4], blo[4][4];
            int aChunk = ks * 2 + (grp >> 1);
            int bChunk = ks * 2 + (grp & 1);
            #pragma unroll
            for (int mt = 0; mt < 2; mt++) {
                uint32_t off = (uint32_t)(wm * 32 + mt * 16 + aRow) * ROWB + aChunk * 16;
                ldsm_x4(ahi[mt], sA + off);
                ldsm_x4(alo[mt], sA + ARRB + off);
            }
            #pragma unroll
            for (int p = 0; p < 4; p++) {
                uint32_t off = (uint32_t)(wn * 64 + p * 16 + bRow) * ROWB + bChunk * 16;
                ldsm_x4(bhi[p], sA + 2 * ARRB + off);
                ldsm_x4(blo[p], sA + 3 * ARRB + off);
            }
            #pragma unroll
            for (int mt = 0; mt < 2; mt++) {
                #pragma unroll
                for (int nt = 0; nt < 8; nt++) {
                    const uint32_t* bh = &bhi[nt >> 1][(nt & 1) * 2];
                    const uint32_t* bl = &blo[nt >> 1][(nt & 1) * 2];
                    float* d = acc[mt][nt];
                    mma_16816(d, ahi[mt], bh);
                    mma_16816(d, ahi[mt], bl);
                    mma_16816(d, alo[mt], bh);
                }
            }
        }
    }

    // ---- epilogue: store C + fused attention dots ----
    const int head = blockIdx.x * 2 + wn;
    const float* av = asrc + head * CH;
    const float* dv = adst + head * CH;
    const int q = lane >> 2, qt = lane & 3;

    #pragma unroll
    for (int mt = 0; mt < 2; mt++) {
        int r0 = rowBase + wm * 32 + mt * 16 + q;
        int r1 = r0 + 8;
        float s0 = 0.f, s1 = 0.f, t0 = 0.f, t1 = 0.f;
        #pragma unroll
        for (int nt = 0; nt < 8; nt++) {
            int lc = nt * 8 + qt * 2;
            float a0v = av[lc], a1v = av[lc + 1];
            float d0v = dv[lc], d1v = dv[lc + 1];
            float* d = acc[mt][nt];
            s0 += d[0] * a0v + d[1] * a1v;  t0 += d[0] * d0v + d[1] * d1v;
            s1 += d[2] * a0v + d[3] * a1v;  t1 += d[2] * d0v + d[3] * d1v;
            long cb = colBase + wn * 64 + lc;
            if (r0 < M) *(float2*)&g_xp[(long)r0 * DIM + cb] = make_float2(d[0], d[1]);
            if (r1 < M) *(float2*)&g_xp[(long)r1 * DIM + cb] = make_float2(d[2], d[3]);
        }
        #pragma unroll
        for (int o = 1; o < 4; o <<= 1) {
            s0 += __shfl_xor_sync(0xFFFFFFFFu, s0, o);
            s1 += __shfl_xor_sync(0xFFFFFFFFu, s1, o);
            t0 += __shfl_xor_sync(0xFFFFFFFFu, t0, o);
            t1 += __shfl_xor_sync(0xFFFFFFFFu, t1, o);
        }
        if (qt == 0) {
            if (r0 < M) { g_as[r0 * HEADS + head] = s0; g_ad[r0 * HEADS + head] = t0; }
            if (r1 < M) { g_as[r1 * HEADS + head] = s1; g_ad[r1 * HEADS + head] = t1; }
        }
    }
}

// ---------------- fused softmax + aggregation (+ layer-specific epilogue) ----------------
// mode 0: += bias1, dropout(key)+ELU+bf16 split -> g_ahi/g_alo (feeds layer-2 GEMM)
// mode 1: head-mean + bias2 -> out
__global__ void k_aggr(const float* __restrict__ bias, float* __restrict__ out,
                       int mode, uint32_t k0, uint32_t k1)
{
    __shared__ float s_alpha[HEADS][32];
    __shared__ int   s_src[HEADS][32];
    __shared__ float red[HEADS][CH];

    int dn = blockIdx.x;
    int h = threadIdx.x >> 5;
    int lane = threadIdx.x & 31;
    int row0 = g_rowptr[dn];
    int deg  = g_rowptr[dn + 1] - row0;
    float advl = g_ad[dn * HEADS + h];

    // pass 1: online max + sum
    float mx = -3.4e38f, sm = 0.0f;
    for (int j = lane; j < deg; j += 32) {
        int sn = g_csrc[row0 + j];
        float e = g_as[sn * HEADS + h] + advl;
        e = (e > 0.0f) ? e : 0.2f * e;
        if (e > mx) { sm = sm * expf(mx - e) + 1.0f; mx = e; }
        else        { sm += expf(e - mx); }
    }
    #pragma unroll
    for (int o = 16; o; o >>= 1) {
        float mo = __shfl_xor_sync(0xFFFFFFFFu, mx, o);
        float so = __shfl_xor_sync(0xFFFFFFFFu, sm, o);
        float M2 = fmaxf(mx, mo);
        sm = sm * expf(mx - M2) + so * expf(mo - M2);
        mx = M2;
    }
    float inv = 1.0f / (sm + 1e-16f);

    // pass 2: alpha-weighted gather-accumulate, smem-staged for MLP
    float ax = 0.0f, ay = 0.0f;
    for (int base = 0; base < deg; base += 32) {
        int j = base + lane;
        float alpha = 0.0f;
        int sn = 0;
        if (j < deg) {
            sn = g_csrc[row0 + j];
            float e = g_as[sn * HEADS + h] + advl;
            e = (e > 0.0f) ? e : 0.2f * e;
            alpha = expf(e - mx) * inv;
        }
        s_alpha[h][lane] = alpha;
        s_src[h][lane]   = sn;
        __syncwarp();
        int cnt = min(32, deg - base);
        #pragma unroll 4
        for (int t = 0; t < cnt; t++) {
            float a  = s_alpha[h][t];
            int   sc = s_src[h][t];
            float2 v = *(const float2*)&g_xp[(long)sc * DIM + h * CH + lane * 2];
            ax = fmaf(a, v.x, ax);
            ay = fmaf(a, v.y, ay);
        }
        __syncwarp();
    }

    if (mode == 0) {
        float res[2] = { ax, ay };
        #pragma unroll
        for (int e2 = 0; e2 < 2; e2++) {
            long idx = (long)dn * DIM + h * CH + lane * 2 + e2;
            float v = res[e2] + bias[(int)(idx & (DIM - 1))];
            v = drop_elu(v, idx, k0, k1);
            __nv_bfloat16 hi = __float2bfloat16(v);
            g_ahi[idx] = hi;
            g_alo[idx] = __float2bfloat16(v - __bfloat162float(hi));
        }
    } else {
        red[h][lane * 2]     = ax;
        red[h][lane * 2 + 1] = ay;
        __syncthreads();
        int c = threadIdx.x;
        if (c < CH) {
            float s = 0.0f;
            #pragma unroll
            for (int hh = 0; hh < HEADS; hh++) s += red[hh][c];
            out[dn * CH + c] = s * 0.125f + bias[c];
        }
    }
}

// ---------------- host orchestration ----------------
extern "C" void kernel_launch(void* const* d_in, const int* in_sizes, int n_in,
                              void* d_out, int out_size)
{
    const float* x   = (const float*)d_in[0];
    const int*   ei  = (const int*)d_in[1];
    const float* W1  = (const float*)d_in[2];
    const float* as1 = (const float*)d_in[3];
    const float* ad1 = (const float*)d_in[4];
    const float* b1  = (const float*)d_in[5];
    const float* W2  = (const float*)d_in[6];
    const float* as2 = (const float*)d_in[7];
    const float* ad2 = (const float*)d_in[8];
    const float* b2  = (const float*)d_in[9];
    float*       out = (float*)d_out;

    uint32_t k1a, k1b, k2a, k2b;
    threefry2x32_fn(0u, 42u, 0u, 0u, k1a, k1b);
    threefry2x32_fn(0u, 42u, 0u, 1u, k2a, k2b);

    const int SMEM_MM = STAGES * STAGEB;   // 163840
    cudaFuncSetAttribute(k_mm, cudaFuncAttributeMaxDynamicSharedMemorySize, SMEM_MM);

    const int elemBlocks = (int)((TOTAL + 255) / 256);
    const int edgeBlocks = (E_TOT + 255) / 256;
    const int nodeBlocks = (N_NODES + 255) / 256;
    const int wBlocks    = (DIM * DIM + 255) / 256;
    dim3 gemmGrid(DIM / 128, (N_NODES + 127) / 128);

    // ---- CSR build (shared by both layers) ----
    k_detect<<<1, 32>>>(ei);
    k_zero<<<nodeBlocks, 256>>>();
    k_count<<<edgeBlocks, 256>>>(ei);
    k_scan1<<<SCAN_BLOCKS, 1024>>>();
    k_scan2<<<1, 32>>>();
    k_scan3<<<nodeBlocks, 256>>>();
    k_fill<<<edgeBlocks, 256>>>(ei);

    // ---- layer 1 ----
    k_wsplit<<<wBlocks, 256>>>(W1);
    k_dropelu<<<elemBlocks, 256>>>(x, k1a, k1b);
    k_mm<<<gemmGrid, 256, SMEM_MM>>>(as1, ad1, N_NODES);
    k_aggr<<<N_NODES, 256>>>(b1, nullptr, 0, k2a, k2b);   // fused bias+dropout+elu+split

    // ---- layer 2 ----
    k_wsplit<<<wBlocks, 256>>>(W2);
    k_mm<<<gemmGrid, 256, SMEM_MM>>>(as2, ad2, N_NODES);
    k_aggr<<<N_NODES, 256>>>(b2, out, 1, 0u, 0u);          // fused mean+bias -> out
}